// round 3
// baseline (speedup 1.0000x reference)
#include <cuda_runtime.h>
#include <stdint.h>

// ==================== problem constants ====================
#define NN   4264      // all_node_num
#define BB   256       // batch
#define NGRP 8
#define GSZ  533       // NN / NGRP
#define MAXD 96        // ELL row capacity (mean deg ~15, P(>96) ~ 0)

// PRNG variant:
//   PRNG_PARTITIONABLE 1 : modern jax (jax_threefry_partitionable=True, default >=0.4.30)
// 32-bit draws in partitionable mode are x0 ^ x1 (jax/_src/prng.py,
// _threefry_random_bits_partitionable).
#define PRNG_PARTITIONABLE 1

// ==================== device scratch (no allocs allowed) ====================
__device__ float g_vals[(size_t)NN * MAXD];
__device__ int   g_cols[(size_t)NN * MAXD];
__device__ int   g_nnz[NN];
__device__ uint2 g_gkeys[256 * NGRP];   // [sweep][group] -> key pair

// ==================== threefry2x32 (exact JAX rounds) ====================
__device__ __forceinline__ uint2 threefry(uint32_t k0, uint32_t k1,
                                          uint32_t x0, uint32_t x1) {
    uint32_t ks2 = k0 ^ k1 ^ 0x1BD11BDAu;
    x0 += k0; x1 += k1;
#define TF_RND(r) { x0 += x1; x1 = (x1 << (r)) | (x1 >> (32 - (r))); x1 ^= x0; }
    TF_RND(13) TF_RND(15) TF_RND(26) TF_RND(6)
    x0 += k1;  x1 += ks2 + 1u;
    TF_RND(17) TF_RND(29) TF_RND(16) TF_RND(24)
    x0 += ks2; x1 += k0 + 2u;
    TF_RND(13) TF_RND(15) TF_RND(26) TF_RND(6)
    x0 += k0;  x1 += k1 + 3u;
    TF_RND(17) TF_RND(29) TF_RND(16) TF_RND(24)
    x0 += k1;  x1 += ks2 + 4u;
    TF_RND(13) TF_RND(15) TF_RND(26) TF_RND(6)
    x0 += ks2; x1 += k0 + 5u;
#undef TF_RND
    return make_uint2(x0, x1);
}

// ==================== XLA EmitFastTanh (bit-replication, CPU & GPU backends) ====
__device__ __forceinline__ float tanh_xla(float x) {
    float ax = fabsf(x);
    float xc = fmaxf(fminf(x, 7.90531110763549805f), -7.90531110763549805f);
    float x2 = xc * xc;
    float p = __fmaf_rn(x2, -2.76076847742355e-16f, 2.00018790482477e-13f);
    p = __fmaf_rn(x2, p, -8.60467152213735e-11f);
    p = __fmaf_rn(x2, p,  5.12229709037114e-08f);
    p = __fmaf_rn(x2, p,  1.48572235717979e-05f);
    p = __fmaf_rn(x2, p,  6.37261928875436e-04f);
    p = __fmaf_rn(x2, p,  4.89352455891786e-03f);
    p = xc * p;
    float q = __fmaf_rn(x2, 1.19825839466702e-06f, 1.18534705686654e-04f);
    q = __fmaf_rn(x2, q, 2.26843463243900e-03f);
    q = __fmaf_rn(x2, q, 4.89352518554385e-03f);
    float r = __fdiv_rn(p, q);
    return (ax < 0.0004f) ? x : r;
}

// ==================== kernel 1: build ELL sparse form of J ====================
// One warp per row, ascending-column order preserved (matters for sum order).
__global__ void build_ell(const float* __restrict__ J) {
    int row = blockIdx.x * (blockDim.x >> 5) + (threadIdx.x >> 5);
    if (row >= NN) return;
    int lane = threadIdx.x & 31;
    const float* Jr = J + (size_t)row * NN;
    int base = 0;
    for (int c0 = 0; c0 < NN; c0 += 32) {
        int c = c0 + lane;
        float v = (c < NN) ? Jr[c] : 0.0f;
        unsigned m = __ballot_sync(0xffffffffu, v != 0.0f);
        if (v != 0.0f) {
            int pos = base + __popc(m & ((1u << lane) - 1u));
            if (pos < MAXD) {
                g_vals[(size_t)row * MAXD + pos] = v;
                g_cols[(size_t)row * MAXD + pos] = c;
            }
        }
        base += __popc(m);
    }
    if (lane == 0) g_nnz[row] = (base < MAXD) ? base : MAXD;
}

// ==================== kernel 2: key schedule ====================
// iter_keys = split(key(42), sn); per sweep: gkeys = split(iter_key, 8)
__global__ void keygen(const int* __restrict__ sn_ptr) {
    if (threadIdx.x != 0 || blockIdx.x != 0) return;
    int sn = *sn_ptr;
    if (sn < 0) sn = 0;
    if (sn > 256) sn = 256;
#if PRNG_PARTITIONABLE
    for (int s = 0; s < sn; s++) {
        uint2 ik = threefry(0u, 42u, 0u, (uint32_t)s);        // foldlike split
        for (int g = 0; g < NGRP; g++) {
            g_gkeys[s * NGRP + g] = threefry(ik.x, ik.y, 0u, (uint32_t)g);
        }
    }
#else
    uint32_t flat[512];
    for (int t = 0; t < sn; t++) {
        uint2 o = threefry(0u, 42u, (uint32_t)t, (uint32_t)(t + sn));
        flat[t] = o.x; flat[t + sn] = o.y;
    }
    for (int s = 0; s < sn; s++) {
        uint32_t ik0 = flat[2 * s], ik1 = flat[2 * s + 1];
        uint32_t f16[16];
        for (int t = 0; t < NGRP; t++) {
            uint2 o = threefry(ik0, ik1, (uint32_t)t, (uint32_t)(t + NGRP));
            f16[t] = o.x; f16[t + NGRP] = o.y;
        }
        for (int g = 0; g < NGRP; g++)
            g_gkeys[s * NGRP + g] = make_uint2(f16[2 * g], f16[2 * g + 1]);
    }
#endif
}

// ==================== kernel 3: Gibbs sweeps, one CTA per chain ====================
__global__ __launch_bounds__(544) void gibbs(
    const float* __restrict__ m_in, const float* __restrict__ H,
    const int* __restrict__ groups, const int* __restrict__ sn_ptr,
    float* __restrict__ out)
{
    __shared__ float ms[NN];
    const int b = blockIdx.x;
    const int tid = threadIdx.x;

    for (int i = tid; i < NN; i += blockDim.x)
        ms[i] = m_in[(size_t)b * NN + i];
    int sn = *sn_ptr;
    if (sn < 0) sn = 0;
    if (sn > 256) sn = 256;
    const bool active = (tid < GSZ);

    // sweep-invariant per-(g,tid) data hoisted to registers
    int   nodeR[NGRP];
    float hR[NGRP];
    int   nnzR[NGRP];
#pragma unroll
    for (int g = 0; g < NGRP; g++) {
        int node = active ? groups[g * GSZ + tid] : 0;
        nodeR[g] = node;
        hR[g]    = active ? H[node] : 0.0f;
        nnzR[g]  = active ? g_nnz[node] : 0;
    }
    __syncthreads();

    for (int s = 0; s < sn; s++) {
#pragma unroll
        for (int g = 0; g < NGRP; g++) {
            float newv = 0.0f;
            const int node = nodeR[g];
            if (active) {
                const int nnz = nnzR[g];
                const float* vp = g_vals + (size_t)node * MAXD;
                const int*   cp = g_cols + (size_t)node * MAXD;
                float acc = 0.0f;
                for (int k = 0; k < nnz; k++)
                    acc = __fmaf_rn(vp[k], ms[cp[k]], acc);   // ascending-col order
                const float I = acc + hR[g];

                const uint2 kk = g_gkeys[s * NGRP + g];
                const uint32_t f = (uint32_t)(b * GSZ + tid);
#if PRNG_PARTITIONABLE
                uint2 o = threefry(kk.x, kk.y, 0u, f);
                const uint32_t bits = o.x ^ o.y;   // 32-bit partitionable draw
#else
                const uint32_t h = (BB * GSZ) / 2;            // 68224
                const uint32_t p = (f < h) ? f : (f - h);
                uint2 o = threefry(kk.x, kk.y, p, p + h);
                const uint32_t bits = (f < h) ? o.x : o.y;
#endif
                const float u = __uint_as_float((bits >> 9) | 0x3f800000u) - 1.0f;
                const float r = u * 2.0f - 1.0f;
                const float d = tanh_xla(I) - r;
                newv = (d > 0.0f) ? 1.0f : ((d < 0.0f) ? -1.0f : 0.0f);
            }
            __syncthreads();          // all reads of ms done before group update
            if (active) ms[node] = newv;
            __syncthreads();
        }
    }

    for (int i = tid; i < NN; i += blockDim.x)
        out[(size_t)b * NN + i] = ms[i];
}

// ==================== launch ====================
extern "C" void kernel_launch(void* const* d_in, const int* in_sizes, int n_in,
                              void* d_out, int out_size) {
    const float* m      = (const float*)d_in[0];
    const float* J      = (const float*)d_in[1];
    const float* H      = (const float*)d_in[2];
    const int*   groups = (const int*)d_in[3];
    const int*   sn     = (const int*)d_in[4];
    float* out          = (float*)d_out;

    (void)in_sizes; (void)n_in; (void)out_size;

    build_ell<<<(NN + 3) / 4, 128>>>(J);      // 4 warps/CTA, warp per row
    keygen<<<1, 1>>>(sn);
    gibbs<<<BB, 544>>>(m, H, groups, sn, out);
}

// round 7
// speedup vs baseline: 4.5029x; 4.5029x over previous
#include <cuda_runtime.h>
#include <stdint.h>

// ==================== problem constants ====================
#define NN    4264      // all_node_num
#define BB    256       // batch
#define NGRP  8
#define GSZ   533       // NN / NGRP
#define KMAX  64        // ELL row capacity (mean deg ~15; 64 = ~12 sigma, unreachable)
#define NWRP  17        // warps per gibbs CTA (544 threads)

#define PRNG_PARTITIONABLE 1

// ==================== device scratch (no allocs allowed) ====================
// transposed ELL: entry (g, k, j) at [(g*KMAX + k)*GSZ + j], packed {val_bits, col}
// +64 pad so inactive lanes (tid in [533,544)) can read harmlessly at any (g,k)
__device__ int2  g_Jt[(size_t)NGRP * KMAX * GSZ + 64];
__device__ int   g_inv[NN];                 // node -> g*GSZ + j
__device__ int   g_nnzt[NGRP * GSZ];        // per (g, j) true nnz
__device__ int   g_kmaxw[NGRP * NWRP];      // per (g, warp) max nnz
__device__ uint2 g_gkeys[256 * NGRP];       // [sweep][group] -> key pair

// ==================== threefry2x32 (exact JAX rounds) ====================
__device__ __forceinline__ uint2 threefry(uint32_t k0, uint32_t k1,
                                          uint32_t x0, uint32_t x1) {
    uint32_t ks2 = k0 ^ k1 ^ 0x1BD11BDAu;
    x0 += k0; x1 += k1;
#define TF_RND(r) { x0 += x1; x1 = (x1 << (r)) | (x1 >> (32 - (r))); x1 ^= x0; }
    TF_RND(13) TF_RND(15) TF_RND(26) TF_RND(6)
    x0 += k1;  x1 += ks2 + 1u;
    TF_RND(17) TF_RND(29) TF_RND(16) TF_RND(24)
    x0 += ks2; x1 += k0 + 2u;
    TF_RND(13) TF_RND(15) TF_RND(26) TF_RND(6)
    x0 += k0;  x1 += k1 + 3u;
    TF_RND(17) TF_RND(29) TF_RND(16) TF_RND(24)
    x0 += k1;  x1 += ks2 + 4u;
    TF_RND(13) TF_RND(15) TF_RND(26) TF_RND(6)
    x0 += ks2; x1 += k0 + 5u;
#undef TF_RND
    return make_uint2(x0, x1);
}

// ==================== XLA EmitFastTanh (bit-replication) ====================
__device__ __forceinline__ float tanh_xla(float x) {
    float ax = fabsf(x);
    float xc = fmaxf(fminf(x, 7.90531110763549805f), -7.90531110763549805f);
    float x2 = xc * xc;
    float p = __fmaf_rn(x2, -2.76076847742355e-16f, 2.00018790482477e-13f);
    p = __fmaf_rn(x2, p, -8.60467152213735e-11f);
    p = __fmaf_rn(x2, p,  5.12229709037114e-08f);
    p = __fmaf_rn(x2, p,  1.48572235717979e-05f);
    p = __fmaf_rn(x2, p,  6.37261928875436e-04f);
    p = __fmaf_rn(x2, p,  4.89352455891786e-03f);
    p = xc * p;
    float q = __fmaf_rn(x2, 1.19825839466702e-06f, 1.18534705686654e-04f);
    q = __fmaf_rn(x2, q, 2.26843463243900e-03f);
    q = __fmaf_rn(x2, q, 4.89352518554385e-03f);
    float r = __fdiv_rn(p, q);
    return (ax < 0.0004f) ? x : r;
}

// ==================== kernel 0: inverse group map ====================
__global__ void inv_map(const int* __restrict__ groups) {
    int p = blockIdx.x * blockDim.x + threadIdx.x;
    if (p < NN) g_inv[groups[p]] = p;
}

// ==================== kernel 1: zero transposed ELL ====================
__global__ void zero_ellt() {
    size_t total = (size_t)NGRP * KMAX * GSZ + 64;
    for (size_t i = blockIdx.x * blockDim.x + threadIdx.x; i < total;
         i += (size_t)gridDim.x * blockDim.x)
        g_Jt[i] = make_int2(0, 0);
}

// ==================== kernel 2: build transposed ELL ====================
// One warp per row; float4 scan; ascending-column order preserved.
__global__ void build_ellt(const float* __restrict__ J) {
    int row = blockIdx.x * (blockDim.x >> 5) + (threadIdx.x >> 5);
    if (row >= NN) return;
    const int lane = threadIdx.x & 31;
    const int p = g_inv[row];
    const int g = p / GSZ, j = p % GSZ;
    const float4* Jr4 = (const float4*)(J + (size_t)row * NN);   // NN % 4 == 0

    int base = 0;
    const int NQ = NN / 4;                     // 1066 float4s
    for (int it = 0; it < (NQ + 31) / 32; it++) {
        int q = it * 32 + lane;
        float4 v = make_float4(0.f, 0.f, 0.f, 0.f);
        if (q < NQ) v = Jr4[q];
        int cnt = (v.x != 0.f) + (v.y != 0.f) + (v.z != 0.f) + (v.w != 0.f);
        // warp inclusive scan of cnt
        int incl = cnt;
#pragma unroll
        for (int off = 1; off < 32; off <<= 1) {
            int n = __shfl_up_sync(0xffffffffu, incl, off);
            if (lane >= off) incl += n;
        }
        int pos = base + (incl - cnt);
        int c0 = q * 4;
        if (v.x != 0.f && pos < KMAX) { g_Jt[(size_t)(g * KMAX + pos) * GSZ + j] = make_int2(__float_as_int(v.x), c0 + 0); pos++; }
        if (v.y != 0.f && pos < KMAX) { g_Jt[(size_t)(g * KMAX + pos) * GSZ + j] = make_int2(__float_as_int(v.y), c0 + 1); pos++; }
        if (v.z != 0.f && pos < KMAX) { g_Jt[(size_t)(g * KMAX + pos) * GSZ + j] = make_int2(__float_as_int(v.z), c0 + 2); pos++; }
        if (v.w != 0.f && pos < KMAX) { g_Jt[(size_t)(g * KMAX + pos) * GSZ + j] = make_int2(__float_as_int(v.w), c0 + 3); pos++; }
        base += __shfl_sync(0xffffffffu, incl, 31);
    }
    if (lane == 0) g_nnzt[g * GSZ + j] = (base < KMAX) ? base : KMAX;
}

// ==================== kernel 3: per-(group, warp) max nnz ====================
__global__ void warp_max_nnz() {
    int tid = threadIdx.x;                 // one CTA, 544 threads
    int w = tid >> 5, lane = tid & 31;
#pragma unroll
    for (int g = 0; g < NGRP; g++) {
        int v = (tid < GSZ) ? g_nnzt[g * GSZ + tid] : 0;
#pragma unroll
        for (int off = 16; off; off >>= 1)
            v = max(v, __shfl_xor_sync(0xffffffffu, v, off));
        if (lane == 0) g_kmaxw[g * NWRP + w] = v;
    }
}

// ==================== kernel 4: key schedule ====================
__global__ void keygen(const int* __restrict__ sn_ptr) {
    if (threadIdx.x != 0 || blockIdx.x != 0) return;
    int sn = *sn_ptr;
    if (sn < 0) sn = 0;
    if (sn > 256) sn = 256;
#if PRNG_PARTITIONABLE
    for (int s = 0; s < sn; s++) {
        uint2 ik = threefry(0u, 42u, 0u, (uint32_t)s);        // foldlike split
        for (int g = 0; g < NGRP; g++)
            g_gkeys[s * NGRP + g] = threefry(ik.x, ik.y, 0u, (uint32_t)g);
    }
#endif
}

// ==================== kernel 5: Gibbs sweeps, one CTA per chain ====================
__global__ __launch_bounds__(544) void gibbs(
    const float* __restrict__ m_in, const float* __restrict__ H,
    const int* __restrict__ groups, const int* __restrict__ sn_ptr,
    float* __restrict__ out)
{
    __shared__ float ms[NN];
    const int b = blockIdx.x;
    const int tid = threadIdx.x;
    const int w = tid >> 5;

    for (int i = tid; i < NN; i += blockDim.x)
        ms[i] = m_in[(size_t)b * NN + i];
    int sn = *sn_ptr;
    if (sn < 0) sn = 0;
    if (sn > 256) sn = 256;
    const bool active = (tid < GSZ);
    const uint32_t f = (uint32_t)(b * GSZ + tid);

    // per-thread / per-warp invariants
    int   nodeR[NGRP];
    float hR[NGRP];
    int   kmw[NGRP];
#pragma unroll
    for (int g = 0; g < NGRP; g++) {
        int node = active ? groups[g * GSZ + tid] : 0;
        nodeR[g] = node;
        hR[g]    = active ? H[node] : 0.0f;
        kmw[g]   = g_kmaxw[g * NWRP + w];   // warp-uniform inner bound
    }
    __syncthreads();

    for (int s = 0; s < sn; s++) {
#pragma unroll
        for (int g = 0; g < NGRP; g++) {
            // PRNG first: long dependent ALU chain overlaps the gather loads
            const uint2 kk = g_gkeys[s * NGRP + g];
            const uint2 o  = threefry(kk.x, kk.y, 0u, f);
            const uint32_t bits = o.x ^ o.y;            // 32-bit partitionable draw
            const float u = __uint_as_float((bits >> 9) | 0x3f800000u) - 1.0f;
            const float r = u * 2.0f - 1.0f;

            // coalesced transposed-ELL gather (padding is exact fp32 no-op)
            const int2* __restrict__ bp = g_Jt + (size_t)(g * KMAX) * GSZ + tid;
            const int km = kmw[g];
            float acc = 0.0f;
            for (int k = 0; k < km; k++) {
                int2 e = bp[(size_t)k * GSZ];
                acc = __fmaf_rn(__int_as_float(e.x), ms[e.y], acc);
            }
            const float I = acc + hR[g];
            const float d = tanh_xla(I) - r;
            const float newv = (d > 0.0f) ? 1.0f : ((d < 0.0f) ? -1.0f : 0.0f);

            __syncthreads();                 // all reads of ms precede group write
            if (active) ms[nodeR[g]] = newv;
            __syncthreads();
        }
    }

    for (int i = tid; i < NN; i += blockDim.x)
        out[(size_t)b * NN + i] = ms[i];
}

// ==================== launch ====================
extern "C" void kernel_launch(void* const* d_in, const int* in_sizes, int n_in,
                              void* d_out, int out_size) {
    const float* m      = (const float*)d_in[0];
    const float* J      = (const float*)d_in[1];
    const float* H      = (const float*)d_in[2];
    const int*   groups = (const int*)d_in[3];
    const int*   sn     = (const int*)d_in[4];
    float* out          = (float*)d_out;
    (void)in_sizes; (void)n_in; (void)out_size;

    inv_map<<<(NN + 255) / 256, 256>>>(groups);
    zero_ellt<<<592, 256>>>();
    build_ellt<<<(NN + 3) / 4, 128>>>(J);     // warp per row, float4 scan
    warp_max_nnz<<<1, 544>>>();
    keygen<<<1, 1>>>(sn);
    gibbs<<<BB, 544>>>(m, H, groups, sn, out);
}

// round 11
// speedup vs baseline: 5.3121x; 1.1797x over previous
#include <cuda_runtime.h>
#include <stdint.h>

// ==================== problem constants ====================
#define NN    4264      // all_node_num
#define BB    256       // batch
#define NGRP  8
#define GSZ   533       // NN / NGRP
#define KMAX  64        // ELL row capacity (mean deg ~15; 64 unreachable)
#define NWRP  17        // warps per gibbs CTA (544 threads)
#define CPB   2         // chains per CTA

// ==================== device scratch (no allocs allowed) ====================
// transposed ELL: entry (g, k, j) at [(g*KMAX + k)*GSZ + j], packed {val_bits, col}
// +64 pad so inactive lanes (tid in [533,544)) read harmlessly at any (g,k)
#define ELLT_TOTAL ((size_t)NGRP * KMAX * GSZ + 64)
__device__ int2  g_Jt[ELLT_TOTAL];
__device__ int   g_inv[NN];                 // node -> g*GSZ + j
__device__ int   g_kmaxw[NGRP * NWRP];      // per (g, gibbs-warp) max nnz
__device__ uint2 g_gkeys[256 * NGRP];       // [sweep][group] -> key pair

// ==================== threefry2x32 (exact JAX rounds) ====================
__device__ __forceinline__ uint2 threefry(uint32_t k0, uint32_t k1,
                                          uint32_t x0, uint32_t x1) {
    uint32_t ks2 = k0 ^ k1 ^ 0x1BD11BDAu;
    x0 += k0; x1 += k1;
#define TF_RND(r) { x0 += x1; x1 = (x1 << (r)) | (x1 >> (32 - (r))); x1 ^= x0; }
    TF_RND(13) TF_RND(15) TF_RND(26) TF_RND(6)
    x0 += k1;  x1 += ks2 + 1u;
    TF_RND(17) TF_RND(29) TF_RND(16) TF_RND(24)
    x0 += ks2; x1 += k0 + 2u;
    TF_RND(13) TF_RND(15) TF_RND(26) TF_RND(6)
    x0 += k0;  x1 += k1 + 3u;
    TF_RND(17) TF_RND(29) TF_RND(16) TF_RND(24)
    x0 += k1;  x1 += ks2 + 4u;
    TF_RND(13) TF_RND(15) TF_RND(26) TF_RND(6)
    x0 += ks2; x1 += k0 + 5u;
#undef TF_RND
    return make_uint2(x0, x1);
}

// ==================== XLA EmitFastTanh (bit-replication) ====================
__device__ __forceinline__ float tanh_xla(float x) {
    float ax = fabsf(x);
    float xc = fmaxf(fminf(x, 7.90531110763549805f), -7.90531110763549805f);
    float x2 = xc * xc;
    float p = __fmaf_rn(x2, -2.76076847742355e-16f, 2.00018790482477e-13f);
    p = __fmaf_rn(x2, p, -8.60467152213735e-11f);
    p = __fmaf_rn(x2, p,  5.12229709037114e-08f);
    p = __fmaf_rn(x2, p,  1.48572235717979e-05f);
    p = __fmaf_rn(x2, p,  6.37261928875436e-04f);
    p = __fmaf_rn(x2, p,  4.89352455891786e-03f);
    p = xc * p;
    float q = __fmaf_rn(x2, 1.19825839466702e-06f, 1.18534705686654e-04f);
    q = __fmaf_rn(x2, q, 2.26843463243900e-03f);
    q = __fmaf_rn(x2, q, 4.89352518554385e-03f);
    float r = __fdiv_rn(p, q);
    return (ax < 0.0004f) ? x : r;
}

// ==================== kernel 0: prep (inverse map + zero scratch) ==========
__global__ void prep(const int* __restrict__ groups) {
    size_t i = (size_t)blockIdx.x * blockDim.x + threadIdx.x;
    size_t stride = (size_t)gridDim.x * blockDim.x;
    for (size_t t = i; t < ELLT_TOTAL; t += stride)
        g_Jt[t] = make_int2(0, 0);
    if (i < NN) g_inv[groups[i]] = (int)i;
    if (i < NGRP * NWRP) g_kmaxw[i] = 0;
}

// ==================== kernel 1: build transposed ELL (+warp max) ===========
// One warp per row; float4 scan; ascending-column order preserved.
__global__ void build_ellt(const float* __restrict__ J) {
    int row = blockIdx.x * (blockDim.x >> 5) + (threadIdx.x >> 5);
    if (row >= NN) return;
    const int lane = threadIdx.x & 31;
    const int p = g_inv[row];
    const int g = p / GSZ, j = p % GSZ;
    const float4* Jr4 = (const float4*)(J + (size_t)row * NN);   // NN % 4 == 0

    int base = 0;
    const int NQ = NN / 4;                     // 1066 float4s
    for (int it = 0; it < (NQ + 31) / 32; it++) {
        int q = it * 32 + lane;
        float4 v = make_float4(0.f, 0.f, 0.f, 0.f);
        if (q < NQ) v = Jr4[q];
        int cnt = (v.x != 0.f) + (v.y != 0.f) + (v.z != 0.f) + (v.w != 0.f);
        int incl = cnt;
#pragma unroll
        for (int off = 1; off < 32; off <<= 1) {
            int n = __shfl_up_sync(0xffffffffu, incl, off);
            if (lane >= off) incl += n;
        }
        int pos = base + (incl - cnt);
        int c0 = q * 4;
        if (v.x != 0.f && pos < KMAX) { g_Jt[(size_t)(g * KMAX + pos) * GSZ + j] = make_int2(__float_as_int(v.x), c0 + 0); pos++; }
        if (v.y != 0.f && pos < KMAX) { g_Jt[(size_t)(g * KMAX + pos) * GSZ + j] = make_int2(__float_as_int(v.y), c0 + 1); pos++; }
        if (v.z != 0.f && pos < KMAX) { g_Jt[(size_t)(g * KMAX + pos) * GSZ + j] = make_int2(__float_as_int(v.z), c0 + 2); pos++; }
        if (v.w != 0.f && pos < KMAX) { g_Jt[(size_t)(g * KMAX + pos) * GSZ + j] = make_int2(__float_as_int(v.w), c0 + 3); pos++; }
        base += __shfl_sync(0xffffffffu, incl, 31);
    }
    if (lane == 0) {
        int nnz = (base < KMAX) ? base : KMAX;
        atomicMax(&g_kmaxw[g * NWRP + (j >> 5)], nnz);
    }
}

// ==================== kernel 2: key schedule (parallel) ====================
__global__ void keygen(const int* __restrict__ sn_ptr) {
    int s = blockIdx.x * blockDim.x + threadIdx.x;
    int sn = *sn_ptr;
    if (sn < 0) sn = 0;
    if (sn > 256) sn = 256;
    if (s < sn) {
        uint2 ik = threefry(0u, 42u, 0u, (uint32_t)s);   // foldlike split
#pragma unroll
        for (int g = 0; g < NGRP; g++)
            g_gkeys[s * NGRP + g] = threefry(ik.x, ik.y, 0u, (uint32_t)g);
    }
}

// ==================== kernel 3: Gibbs sweeps, 2 chains per CTA =============
__global__ __launch_bounds__(544) void gibbs(
    const float* __restrict__ m_in, const float* __restrict__ H,
    const int* __restrict__ groups, const int* __restrict__ sn_ptr,
    float* __restrict__ out)
{
    __shared__ float2 ms[NN];                 // .x = chain b0, .y = chain b1
    const int b0 = blockIdx.x * CPB;
    const int b1 = b0 + 1;
    const int tid = threadIdx.x;
    const int w = tid >> 5;

    for (int i = tid; i < NN; i += blockDim.x)
        ms[i] = make_float2(m_in[(size_t)b0 * NN + i], m_in[(size_t)b1 * NN + i]);
    int sn = *sn_ptr;
    if (sn < 0) sn = 0;
    if (sn > 256) sn = 256;
    const bool active = (tid < GSZ);
    const uint32_t f0 = (uint32_t)(b0 * GSZ + tid);
    const uint32_t f1 = f0 + GSZ;

    // per-thread / per-warp invariants
    int   nodeR[NGRP];
    float hR[NGRP];
    int   kmw[NGRP];
#pragma unroll
    for (int g = 0; g < NGRP; g++) {
        int node = active ? groups[g * GSZ + tid] : 0;
        nodeR[g] = node;
        hR[g]    = active ? H[node] : 0.0f;
        kmw[g]   = g_kmaxw[g * NWRP + w];     // warp-uniform inner bound
    }
    __syncthreads();

    for (int s = 0; s < sn; s++) {
#pragma unroll
        for (int g = 0; g < NGRP; g++) {
            // PRNG first: two independent ALU chains overlap the gather loads
            const uint2 kk = g_gkeys[s * NGRP + g];
            const uint2 oA = threefry(kk.x, kk.y, 0u, f0);
            const uint2 oB = threefry(kk.x, kk.y, 0u, f1);
            const uint32_t bA = oA.x ^ oA.y;
            const uint32_t bB = oB.x ^ oB.y;
            const float r0 = (__uint_as_float((bA >> 9) | 0x3f800000u) - 1.0f) * 2.0f - 1.0f;
            const float r1 = (__uint_as_float((bB >> 9) | 0x3f800000u) - 1.0f) * 2.0f - 1.0f;

            // coalesced transposed-ELL gather; one entry feeds both chains
            const int2* __restrict__ bp = g_Jt + (size_t)(g * KMAX) * GSZ + tid;
            const int km = kmw[g];
            float acc0 = 0.0f, acc1 = 0.0f;
            for (int k = 0; k < km; k++) {
                int2 e = bp[(size_t)k * GSZ];
                float2 mv = ms[e.y];                       // one LDS.64, 2 chains
                float v = __int_as_float(e.x);
                acc0 = __fmaf_rn(v, mv.x, acc0);
                acc1 = __fmaf_rn(v, mv.y, acc1);
            }
            const float d0 = tanh_xla(acc0 + hR[g]) - r0;
            const float d1 = tanh_xla(acc1 + hR[g]) - r1;
            const float n0 = (d0 > 0.0f) ? 1.0f : ((d0 < 0.0f) ? -1.0f : 0.0f);
            const float n1 = (d1 > 0.0f) ? 1.0f : ((d1 < 0.0f) ? -1.0f : 0.0f);

            __syncthreads();                  // all reads of ms precede write
            if (active) ms[nodeR[g]] = make_float2(n0, n1);
            __syncthreads();
        }
    }

    for (int i = tid; i < NN; i += blockDim.x) {
        float2 v = ms[i];
        out[(size_t)b0 * NN + i] = v.x;
        out[(size_t)b1 * NN + i] = v.y;
    }
}

// ==================== launch ====================
extern "C" void kernel_launch(void* const* d_in, const int* in_sizes, int n_in,
                              void* d_out, int out_size) {
    const float* m      = (const float*)d_in[0];
    const float* J      = (const float*)d_in[1];
    const float* H      = (const float*)d_in[2];
    const int*   groups = (const int*)d_in[3];
    const int*   sn     = (const int*)d_in[4];
    float* out          = (float*)d_out;
    (void)in_sizes; (void)n_in; (void)out_size;

    prep<<<(int)((ELLT_TOTAL + 255) / 256), 256>>>(groups);
    build_ellt<<<(NN + 3) / 4, 128>>>(J);     // warp per row, float4 scan
    keygen<<<1, 256>>>(sn);
    gibbs<<<BB / CPB, 544>>>(m, H, groups, sn, out);
}